// round 1
// baseline (speedup 1.0000x reference)
#include <cuda_runtime.h>
#include <cuda_bf16.h>
#include <math.h>

// Problem constants (fixed by the reference)
#define BATCH 4
#define SEQ   2048
#define T     (BATCH*SEQ)      // 8192 tokens
#define C     512
#define FF    2048
#define E     8
#define TOPK  2
#define TK    (T*TOPK)         // 16384 assignments

// ---------------- scratch (no allocations allowed) ----------------
__device__ float g_H[(size_t)TK * FF];   // gelu(X@W1^T) per assignment, 134MB
__device__ float g_P[(size_t)TK * C];    // weighted expert output per assignment, 33.5MB
__device__ int   g_topi[TK];
__device__ float g_topw[TK];
__device__ int   g_perm[TK];             // gathered order -> token index
__device__ float g_pw[TK];               // gathered order -> routing weight
__device__ int   g_tokslot[TK];          // (token,k) -> gathered position
__device__ int   g_counts[E];
__device__ int   g_offsets[E + 1];
__device__ int   g_cursor[E];

// ---------------- kernel 0: reset counters ----------------
__global__ void reset_kernel() {
    int i = threadIdx.x;
    if (i < E) g_counts[i] = 0;
}

// ---------------- kernel 1: router (one warp per token) ----------------
__global__ void router_kernel(const float* __restrict__ x,
                              const float* __restrict__ rw) {
    __shared__ float s_rw[E * C];                 // 16KB
    int tid = threadIdx.x;
    for (int i = tid; i < E * C; i += blockDim.x) s_rw[i] = rw[i];
    __syncthreads();

    int warp = tid >> 5;
    int lane = tid & 31;
    int t = blockIdx.x * 8 + warp;
    if (t >= T) return;

    float acc[E];
#pragma unroll
    for (int e = 0; e < E; e++) acc[e] = 0.f;

    const float* xr = x + (size_t)t * C;
    for (int c = lane; c < C; c += 32) {
        float xv = xr[c];
#pragma unroll
        for (int e = 0; e < E; e++) acc[e] += xv * s_rw[e * C + c];
    }
#pragma unroll
    for (int e = 0; e < E; e++) {
#pragma unroll
        for (int off = 16; off > 0; off >>= 1)
            acc[e] += __shfl_xor_sync(0xffffffffu, acc[e], off);
    }
    if (lane == 0) {
        float m = acc[0];
#pragma unroll
        for (int e = 1; e < E; e++) m = fmaxf(m, acc[e]);
        float p[E], s = 0.f;
#pragma unroll
        for (int e = 0; e < E; e++) { p[e] = expf(acc[e] - m); s += p[e]; }
        // top-2 (first occurrence wins ties, like lax.top_k)
        int i0 = 0;
#pragma unroll
        for (int e = 1; e < E; e++) if (p[e] > p[i0]) i0 = e;
        int i1 = (i0 == 0) ? 1 : 0;
#pragma unroll
        for (int e = 0; e < E; e++) if (e != i0 && p[e] > p[i1]) i1 = e;
        float w0 = p[i0] / s, w1 = p[i1] / s;
        float norm = w0 + w1 + 1e-9f;
        w0 /= norm; w1 /= norm;
        g_topi[t * 2 + 0] = i0;  g_topw[t * 2 + 0] = w0;
        g_topi[t * 2 + 1] = i1;  g_topw[t * 2 + 1] = w1;
        atomicAdd(&g_counts[i0], 1);
        atomicAdd(&g_counts[i1], 1);
    }
}

// ---------------- kernel 2: exclusive scan over 8 counts ----------------
__global__ void scan_kernel() {
    if (threadIdx.x == 0) {
        int off = 0;
        for (int e = 0; e < E; e++) {
            g_offsets[e] = off;
            g_cursor[e]  = off;
            off += g_counts[e];
        }
        g_offsets[E] = off;
    }
}

// ---------------- kernel 3: scatter assignments into expert buckets ----------------
__global__ void scatter_kernel() {
    int idx = blockIdx.x * blockDim.x + threadIdx.x;
    if (idx >= TK) return;
    int t = idx >> 1;
    int e = g_topi[idx];
    int p = atomicAdd(&g_cursor[e], 1);
    g_perm[p] = t;
    g_pw[p]   = g_topw[idx];
    g_tokslot[idx] = p;
}

// ---------------- GEMM helpers ----------------
__device__ __forceinline__ float gelu_exact(float v) {
    return 0.5f * v * (1.0f + erff(v * 0.7071067811865476f));
}

// Classic 128x128x8 SGEMM tile, 256 threads, 8x8 per thread.
// GEMM1: H[g, ff] = gelu( sum_c X[perm[g], c] * W1[e, ff, c] + b1[e, ff] )
__global__ __launch_bounds__(256)
void gemm1_kernel(const float* __restrict__ x,
                  const float* __restrict__ w1,
                  const float* __restrict__ b1) {
    const int e = blockIdx.z;
    const int gstart = g_offsets[e];
    const int gend   = g_offsets[e + 1];
    const int gbase  = gstart + blockIdx.y * 128;
    if (gbase >= gend) return;
    const int ffbase = blockIdx.x * 128;

    __shared__ float As[8][128];
    __shared__ float Bs[8][128];

    const int tid = threadIdx.x;
    const int a_row = tid >> 1;              // 0..127
    const int a_col = (tid & 1) * 4;         // 0 or 4
    const int tx = tid & 15;                 // col tile
    const int ty = tid >> 4;                 // row tile

    // gather: resolve this thread's A row token once
    const int g_row = gbase + a_row;
    const bool row_ok = (g_row < gend);
    const int token = row_ok ? g_perm[g_row] : 0;
    const float* __restrict__ aptr = x + (size_t)token * C;
    const float* __restrict__ bptr = w1 + ((size_t)e * FF + ffbase + a_row) * C;

    float acc[8][8];
#pragma unroll
    for (int i = 0; i < 8; i++)
#pragma unroll
        for (int j = 0; j < 8; j++) acc[i][j] = 0.f;

    for (int k0 = 0; k0 < C; k0 += 8) {
        float4 av = row_ok ? *(const float4*)(aptr + k0 + a_col)
                           : make_float4(0.f, 0.f, 0.f, 0.f);
        float4 bv = *(const float4*)(bptr + k0 + a_col);
        As[a_col + 0][a_row] = av.x; As[a_col + 1][a_row] = av.y;
        As[a_col + 2][a_row] = av.z; As[a_col + 3][a_row] = av.w;
        Bs[a_col + 0][a_row] = bv.x; Bs[a_col + 1][a_row] = bv.y;
        Bs[a_col + 2][a_row] = bv.z; Bs[a_col + 3][a_row] = bv.w;
        __syncthreads();
#pragma unroll
        for (int k = 0; k < 8; k++) {
            float4 a0 = *(const float4*)&As[k][ty * 8];
            float4 a1 = *(const float4*)&As[k][ty * 8 + 4];
            float4 b0 = *(const float4*)&Bs[k][tx * 8];
            float4 b1v = *(const float4*)&Bs[k][tx * 8 + 4];
            float ra[8] = {a0.x, a0.y, a0.z, a0.w, a1.x, a1.y, a1.z, a1.w};
            float rb[8] = {b0.x, b0.y, b0.z, b0.w, b1v.x, b1v.y, b1v.z, b1v.w};
#pragma unroll
            for (int i = 0; i < 8; i++)
#pragma unroll
                for (int j = 0; j < 8; j++) acc[i][j] += ra[i] * rb[j];
        }
        __syncthreads();
    }

    float bias[8];
#pragma unroll
    for (int j = 0; j < 8; j++) bias[j] = b1[(size_t)e * FF + ffbase + tx * 8 + j];

#pragma unroll
    for (int i = 0; i < 8; i++) {
        int g = gbase + ty * 8 + i;
        if (g < gend) {
            float* hp = g_H + (size_t)g * FF + ffbase + tx * 8;
            float4 v0, v1;
            v0.x = gelu_exact(acc[i][0] + bias[0]);
            v0.y = gelu_exact(acc[i][1] + bias[1]);
            v0.z = gelu_exact(acc[i][2] + bias[2]);
            v0.w = gelu_exact(acc[i][3] + bias[3]);
            v1.x = gelu_exact(acc[i][4] + bias[4]);
            v1.y = gelu_exact(acc[i][5] + bias[5]);
            v1.z = gelu_exact(acc[i][6] + bias[6]);
            v1.w = gelu_exact(acc[i][7] + bias[7]);
            *(float4*)(hp) = v0;
            *(float4*)(hp + 4) = v1;
        }
    }
}

// GEMM2: P[g, c] = pw[g] * ( sum_ff H[g, ff] * W2[e, c, ff] + b2[e, c] )
__global__ __launch_bounds__(256)
void gemm2_kernel(const float* __restrict__ w2,
                  const float* __restrict__ b2) {
    const int e = blockIdx.z;
    const int gstart = g_offsets[e];
    const int gend   = g_offsets[e + 1];
    const int gbase  = gstart + blockIdx.y * 128;
    if (gbase >= gend) return;
    const int cbase = blockIdx.x * 128;

    __shared__ float As[8][128];
    __shared__ float Bs[8][128];

    const int tid = threadIdx.x;
    const int a_row = tid >> 1;
    const int a_col = (tid & 1) * 4;
    const int tx = tid & 15;
    const int ty = tid >> 4;

    const int g_row = gbase + a_row;
    const bool row_ok = (g_row < gend);
    const float* __restrict__ aptr = g_H + (size_t)(row_ok ? g_row : gbase) * FF;
    const float* __restrict__ bptr = w2 + ((size_t)e * C + cbase + a_row) * FF;

    float acc[8][8];
#pragma unroll
    for (int i = 0; i < 8; i++)
#pragma unroll
        for (int j = 0; j < 8; j++) acc[i][j] = 0.f;

    for (int k0 = 0; k0 < FF; k0 += 8) {
        float4 av = row_ok ? *(const float4*)(aptr + k0 + a_col)
                           : make_float4(0.f, 0.f, 0.f, 0.f);
        float4 bv = *(const float4*)(bptr + k0 + a_col);
        As[a_col + 0][a_row] = av.x; As[a_col + 1][a_row] = av.y;
        As[a_col + 2][a_row] = av.z; As[a_col + 3][a_row] = av.w;
        Bs[a_col + 0][a_row] = bv.x; Bs[a_col + 1][a_row] = bv.y;
        Bs[a_col + 2][a_row] = bv.z; Bs[a_col + 3][a_row] = bv.w;
        __syncthreads();
#pragma unroll
        for (int k = 0; k < 8; k++) {
            float4 a0 = *(const float4*)&As[k][ty * 8];
            float4 a1 = *(const float4*)&As[k][ty * 8 + 4];
            float4 b0 = *(const float4*)&Bs[k][tx * 8];
            float4 b1v = *(const float4*)&Bs[k][tx * 8 + 4];
            float ra[8] = {a0.x, a0.y, a0.z, a0.w, a1.x, a1.y, a1.z, a1.w};
            float rb[8] = {b0.x, b0.y, b0.z, b0.w, b1v.x, b1v.y, b1v.z, b1v.w};
#pragma unroll
            for (int i = 0; i < 8; i++)
#pragma unroll
                for (int j = 0; j < 8; j++) acc[i][j] += ra[i] * rb[j];
        }
        __syncthreads();
    }

    float bias[8];
#pragma unroll
    for (int j = 0; j < 8; j++) bias[j] = b2[(size_t)e * C + cbase + tx * 8 + j];

#pragma unroll
    for (int i = 0; i < 8; i++) {
        int g = gbase + ty * 8 + i;
        if (g < gend) {
            float w = g_pw[g];
            float* pp = g_P + (size_t)g * C + cbase + tx * 8;
            float4 v0, v1;
            v0.x = w * (acc[i][0] + bias[0]);
            v0.y = w * (acc[i][1] + bias[1]);
            v0.z = w * (acc[i][2] + bias[2]);
            v0.w = w * (acc[i][3] + bias[3]);
            v1.x = w * (acc[i][4] + bias[4]);
            v1.y = w * (acc[i][5] + bias[5]);
            v1.z = w * (acc[i][6] + bias[6]);
            v1.w = w * (acc[i][7] + bias[7]);
            *(float4*)(pp) = v0;
            *(float4*)(pp + 4) = v1;
        }
    }
}

// ---------------- kernel 6: combine the two slots per token ----------------
__global__ void combine_kernel(float* __restrict__ out) {
    int i4 = blockIdx.x * blockDim.x + threadIdx.x;   // float4 index
    const int C4 = C / 4;
    if (i4 >= T * C4) return;
    int t  = i4 / C4;
    int c4 = i4 - t * C4;
    int p0 = g_tokslot[t * 2 + 0];
    int p1 = g_tokslot[t * 2 + 1];
    const float4* P4 = (const float4*)g_P;
    float4 a = P4[(size_t)p0 * C4 + c4];
    float4 b = P4[(size_t)p1 * C4 + c4];
    float4 r;
    r.x = a.x + b.x; r.y = a.y + b.y; r.z = a.z + b.z; r.w = a.w + b.w;
    ((float4*)out)[i4] = r;
}

// ---------------- launch ----------------
extern "C" void kernel_launch(void* const* d_in, const int* in_sizes, int n_in,
                              void* d_out, int out_size) {
    const float* x  = (const float*)d_in[0];   // [T, C]
    const float* rw = (const float*)d_in[1];   // [E, C]
    const float* w1 = (const float*)d_in[2];   // [E, FF, C]
    const float* b1 = (const float*)d_in[3];   // [E, FF]
    const float* w2 = (const float*)d_in[4];   // [E, C, FF]
    const float* b2 = (const float*)d_in[5];   // [E, C]
    float* out = (float*)d_out;

    reset_kernel<<<1, 32>>>();
    router_kernel<<<T / 8, 256>>>(x, rw);
    scan_kernel<<<1, 32>>>();
    scatter_kernel<<<(TK + 255) / 256, 256>>>();
    gemm1_kernel<<<dim3(FF / 128, 128, E), 256>>>(x, w1, b1);
    gemm2_kernel<<<dim3(C / 128, 128, E), 256>>>(w2, b2);
    combine_kernel<<<(T * (C / 4) + 255) / 256, 256>>>(out);
}

// round 5
// speedup vs baseline: 2.3856x; 2.3856x over previous
#include <cuda_runtime.h>
#include <cstdint>
#include <math.h>

// ---------------- problem constants ----------------
#define T_TOK 8192
#define C     512
#define FF    2048
#define E     8
#define TK    16384            // T*2 assignments

// ---------------- scratch ----------------
__device__ float g_H[(size_t)TK * FF];   // gelu(X@W1^T) per assignment (134MB)
__device__ int   g_topi[TK];
__device__ float g_topw[TK];
__device__ int   g_perm[TK];             // gathered order -> token index
__device__ float g_pw[TK];               // gathered order -> routing weight
__device__ int   g_counts[E];
__device__ int   g_offsets[E + 1];
__device__ int   g_cursor[E];

// ---------------- helpers ----------------
__device__ __forceinline__ uint32_t smem_u32(const void* p) {
    uint32_t a;
    asm("{ .reg .u64 t; cvta.to.shared.u64 t, %1; cvt.u32.u64 %0, t; }"
        : "=r"(a) : "l"(p));
    return a;
}
__device__ __forceinline__ void cp16(uint32_t dst, const void* src) {
    asm volatile("cp.async.cg.shared.global [%0], [%1], 16;" :: "r"(dst), "l"(src));
}
__device__ __forceinline__ void cp_commit() {
    asm volatile("cp.async.commit_group;" ::: "memory");
}
template <int N> __device__ __forceinline__ void cp_wait() {
    asm volatile("cp.async.wait_group %0;" :: "n"(N) : "memory");
}
__device__ __forceinline__ uint32_t f2tf(float f) {
    uint32_t r;
    asm("cvt.rna.tf32.f32 %0, %1;" : "=r"(r) : "f"(f));
    return r;
}
__device__ __forceinline__ void mma8(float* d, const uint32_t* a, const uint32_t* b) {
    asm volatile(
        "mma.sync.aligned.m16n8k8.row.col.f32.tf32.tf32.f32 "
        "{%0,%1,%2,%3}, {%4,%5,%6,%7}, {%8,%9}, {%0,%1,%2,%3};"
        : "+f"(d[0]), "+f"(d[1]), "+f"(d[2]), "+f"(d[3])
        : "r"(a[0]), "r"(a[1]), "r"(a[2]), "r"(a[3]), "r"(b[0]), "r"(b[1]));
}
__device__ __forceinline__ float gelu_exact(float v) {
    return 0.5f * v * (1.0f + erff(v * 0.7071067811865476f));
}

// ---------------- small kernels ----------------
__global__ void reset_kernel() {
    int i = threadIdx.x;
    if (i < E) g_counts[i] = 0;
}

__global__ void zero_out_kernel(float4* out) {
    int i = blockIdx.x * blockDim.x + threadIdx.x;
    if (i < T_TOK * (C / 4)) out[i] = make_float4(0.f, 0.f, 0.f, 0.f);
}

__global__ void router_kernel(const float* __restrict__ x,
                              const float* __restrict__ rw) {
    __shared__ float s_rw[E * C];
    int tid = threadIdx.x;
    for (int i = tid; i < E * C; i += blockDim.x) s_rw[i] = rw[i];
    __syncthreads();

    int warp = tid >> 5, lane = tid & 31;
    int t = blockIdx.x * 8 + warp;
    if (t >= T_TOK) return;

    float acc[E];
#pragma unroll
    for (int e = 0; e < E; e++) acc[e] = 0.f;
    const float* xr = x + (size_t)t * C;
    for (int c = lane; c < C; c += 32) {
        float xv = xr[c];
#pragma unroll
        for (int e = 0; e < E; e++) acc[e] += xv * s_rw[e * C + c];
    }
#pragma unroll
    for (int e = 0; e < E; e++)
#pragma unroll
        for (int off = 16; off > 0; off >>= 1)
            acc[e] += __shfl_xor_sync(0xffffffffu, acc[e], off);
    if (lane == 0) {
        float m = acc[0];
#pragma unroll
        for (int e = 1; e < E; e++) m = fmaxf(m, acc[e]);
        float p[E], s = 0.f;
#pragma unroll
        for (int e = 0; e < E; e++) { p[e] = expf(acc[e] - m); s += p[e]; }
        int i0 = 0;
#pragma unroll
        for (int e = 1; e < E; e++) if (p[e] > p[i0]) i0 = e;
        int i1 = (i0 == 0) ? 1 : 0;
#pragma unroll
        for (int e = 0; e < E; e++) if (e != i0 && p[e] > p[i1]) i1 = e;
        float w0 = p[i0] / s, w1 = p[i1] / s;
        float norm = w0 + w1 + 1e-9f;
        w0 /= norm; w1 /= norm;
        g_topi[t * 2 + 0] = i0;  g_topw[t * 2 + 0] = w0;
        g_topi[t * 2 + 1] = i1;  g_topw[t * 2 + 1] = w1;
        atomicAdd(&g_counts[i0], 1);
        atomicAdd(&g_counts[i1], 1);
    }
}

__global__ void scan_kernel() {
    if (threadIdx.x == 0) {
        int off = 0;
        for (int e = 0; e < E; e++) {
            g_offsets[e] = off;
            g_cursor[e]  = off;
            off += g_counts[e];
        }
        g_offsets[E] = off;
    }
}

__global__ void scatter_kernel() {
    int idx = blockIdx.x * blockDim.x + threadIdx.x;
    if (idx >= TK) return;
    int t = idx >> 1;
    int e = g_topi[idx];
    int p = atomicAdd(&g_cursor[e], 1);
    g_perm[p] = t;
    g_pw[p]   = g_topw[idx];
}

// ---------------- tf32 mma.sync grouped GEMMs ----------------
// CTA tile 128x128x32, 8 warps (2x4), warp tile 64x32, m16n8k8 tf32.
#define BM 128
#define BN 128
#define BK 32
#define LROW 36                          // padded row: 32 + 4 floats
#define STG_FLT (BM * LROW)              // 4608 floats per tile-stage
#define GEMM_SMEM_BYTES (4 * STG_FLT * 4)  // A0,A1,B0,B1 = 73728 B

// GEMM1: g_H[g, ff] = gelu( X[perm[g]] @ W1[e]^T + b1[e] )
__global__ __launch_bounds__(256, 1)
void gemm1_mma(const float* __restrict__ x,
               const float* __restrict__ w1,
               const float* __restrict__ b1) {
    const int e = blockIdx.z;
    const int gstart = g_offsets[e], gend = g_offsets[e + 1];
    const int gbase = gstart + blockIdx.y * BM;
    if (gbase >= gend) return;
    const int nbase = blockIdx.x * BN;

    extern __shared__ float dsm[];
    float* const A0 = dsm;
    float* const A1 = dsm + STG_FLT;
    float* const B0 = dsm + 2 * STG_FLT;
    float* const B1 = dsm + 3 * STG_FLT;
    __shared__ float s_bias[BN];

    const int tid = threadIdx.x;
    if (tid < BN) s_bias[tid] = b1[(size_t)e * FF + nbase + tid];

    // ---- loader mapping: thread -> (row, half-row of 16 floats) ----
    const int lrow = tid >> 1;
    const int lq   = (tid & 1) * 16;
    const int ga = gbase + lrow;
    const int tok = (ga < gend) ? g_perm[ga] : 0;
    const float* aSrc = x + (size_t)tok * C + lq;
    const float* bSrc = w1 + ((size_t)e * FF + nbase + lrow) * C + lq;
    const uint32_t aD0 = smem_u32(A0 + lrow * LROW + lq);
    const uint32_t aD1 = smem_u32(A1 + lrow * LROW + lq);
    const uint32_t bD0 = smem_u32(B0 + lrow * LROW + lq);
    const uint32_t bD1 = smem_u32(B1 + lrow * LROW + lq);

    // ---- compute mapping ----
    const int w = tid >> 5, lane = tid & 31;
    const int wm = w >> 2, wn = w & 3;
    const int gid = lane >> 2, tig = lane & 3;

    float acc[4][4][4];
#pragma unroll
    for (int i = 0; i < 4; i++)
#pragma unroll
        for (int j = 0; j < 4; j++)
#pragma unroll
            for (int r = 0; r < 4; r++) acc[i][j][r] = 0.f;

    // prologue: chunk 0 -> stage 0
#pragma unroll
    for (int i = 0; i < 4; i++) cp16(aD0 + i * 16, aSrc + i * 4);
#pragma unroll
    for (int i = 0; i < 4; i++) cp16(bD0 + i * 16, bSrc + i * 4);
    cp_commit();

    const int NCH = C / BK;  // 16
    for (int k = 0; k < NCH; k++) {
        const int s = k & 1;
        if (k + 1 < NCH) {
            const float* aS = aSrc + (k + 1) * BK;
            const float* bS = bSrc + (k + 1) * BK;
            const uint32_t ad = (s == 0) ? aD1 : aD0;
            const uint32_t bd = (s == 0) ? bD1 : bD0;
#pragma unroll
            for (int i = 0; i < 4; i++) cp16(ad + i * 16, aS + i * 4);
#pragma unroll
            for (int i = 0; i < 4; i++) cp16(bd + i * 16, bS + i * 4);
            cp_commit();
            cp_wait<1>();
        } else {
            cp_wait<0>();
        }
        __syncthreads();
        const float* Asb = (s == 0) ? A0 : A1;
        const float* Bsb = (s == 0) ? B0 : B1;
#pragma unroll
        for (int ks = 0; ks < 4; ks++) {
            const int kc = ks * 8;
            uint32_t af[4][4], bf[4][2];
#pragma unroll
            for (int mt = 0; mt < 4; mt++) {
                const float* p = Asb + (wm * 64 + mt * 16 + gid) * LROW + kc + tig;
                af[mt][0] = f2tf(p[0]);
                af[mt][1] = f2tf(p[8 * LROW]);
                af[mt][2] = f2tf(p[4]);
                af[mt][3] = f2tf(p[8 * LROW + 4]);
            }
#pragma unroll
            for (int nt = 0; nt < 4; nt++) {
                const float* p = Bsb + (wn * 32 + nt * 8 + gid) * LROW + kc + tig;
                bf[nt][0] = f2tf(p[0]);
                bf[nt][1] = f2tf(p[4]);
            }
#pragma unroll
            for (int mt = 0; mt < 4; mt++)
#pragma unroll
                for (int nt = 0; nt < 4; nt++)
                    mma8(acc[mt][nt], af[mt], bf[nt]);
        }
        __syncthreads();
    }

    // epilogue: bias + exact gelu -> g_H
#pragma unroll
    for (int mt = 0; mt < 4; mt++) {
        const int r0 = wm * 64 + mt * 16 + gid;
        const int gr0 = gbase + r0, gr1 = gr0 + 8;
#pragma unroll
        for (int nt = 0; nt < 4; nt++) {
            const int col = wn * 32 + nt * 8 + tig * 2;
            const float b0v = s_bias[col], b1v = s_bias[col + 1];
            if (gr0 < gend) {
                float2 v;
                v.x = gelu_exact(acc[mt][nt][0] + b0v);
                v.y = gelu_exact(acc[mt][nt][1] + b1v);
                *(float2*)(g_H + (size_t)gr0 * FF + nbase + col) = v;
            }
            if (gr1 < gend) {
                float2 v;
                v.x = gelu_exact(acc[mt][nt][2] + b0v);
                v.y = gelu_exact(acc[mt][nt][3] + b1v);
                *(float2*)(g_H + (size_t)gr1 * FF + nbase + col) = v;
            }
        }
    }
}

// GEMM2: out[token] += pw[g] * ( g_H[g] @ W2[e]^T + b2[e] )
__global__ __launch_bounds__(256, 1)
void gemm2_mma(const float* __restrict__ w2,
               const float* __restrict__ b2,
               float* __restrict__ out) {
    const int e = blockIdx.z;
    const int gstart = g_offsets[e], gend = g_offsets[e + 1];
    const int gbase = gstart + blockIdx.y * BM;
    if (gbase >= gend) return;
    const int nbase = blockIdx.x * BN;

    extern __shared__ float dsm[];
    float* const A0 = dsm;
    float* const A1 = dsm + STG_FLT;
    float* const B0 = dsm + 2 * STG_FLT;
    float* const B1 = dsm + 3 * STG_FLT;
    __shared__ float s_bias[BN];

    const int tid = threadIdx.x;
    if (tid < BN) s_bias[tid] = b2[(size_t)e * C + nbase + tid];

    const int lrow = tid >> 1;
    const int lq   = (tid & 1) * 16;
    int ga = gbase + lrow; if (ga > TK - 1) ga = TK - 1;
    const float* aSrc = g_H + (size_t)ga * FF + lq;
    const float* bSrc = w2 + ((size_t)e * C + nbase + lrow) * FF + lq;
    const uint32_t aD0 = smem_u32(A0 + lrow * LROW + lq);
    const uint32_t aD1 = smem_u32(A1 + lrow * LROW + lq);
    const uint32_t bD0 = smem_u32(B0 + lrow * LROW + lq);
    const uint32_t bD1 = smem_u32(B1 + lrow * LROW + lq);

    const int w = tid >> 5, lane = tid & 31;
    const int wm = w >> 2, wn = w & 3;
    const int gid = lane >> 2, tig = lane & 3;

    float acc[4][4][4];
#pragma unroll
    for (int i = 0; i < 4; i++)
#pragma unroll
        for (int j = 0; j < 4; j++)
#pragma unroll
            for (int r = 0; r < 4; r++) acc[i][j][r] = 0.f;

#pragma unroll
    for (int i = 0; i < 4; i++) cp16(aD0 + i * 16, aSrc + i * 4);
#pragma unroll
    for (int i = 0; i < 4; i++) cp16(bD0 + i * 16, bSrc + i * 4);
    cp_commit();

    const int NCH = FF / BK;  // 64
    for (int k = 0; k < NCH; k++) {
        const int s = k & 1;
        if (k + 1 < NCH) {
            const float* aS = aSrc + (k + 1) * BK;
            const float* bS = bSrc + (k + 1) * BK;
            const uint32_t ad = (s == 0) ? aD1 : aD0;
            const uint32_t bd = (s == 0) ? bD1 : bD0;
#pragma unroll
            for (int i = 0; i < 4; i++) cp16(ad + i * 16, aS + i * 4);
#pragma unroll
            for (int i = 0; i < 4; i++) cp16(bd + i * 16, bS + i * 4);
            cp_commit();
            cp_wait<1>();
        } else {
            cp_wait<0>();
        }
        __syncthreads();
        const float* Asb = (s == 0) ? A0 : A1;
        const float* Bsb = (s == 0) ? B0 : B1;
#pragma unroll
        for (int ks = 0; ks < 4; ks++) {
            const int kc = ks * 8;
            uint32_t af[4][4], bf[4][2];
#pragma unroll
            for (int mt = 0; mt < 4; mt++) {
                const float* p = Asb + (wm * 64 + mt * 16 + gid) * LROW + kc + tig;
                af[mt][0] = f2tf(p[0]);
                af[mt][1] = f2tf(p[8 * LROW]);
                af[mt][2] = f2tf(p[4]);
                af[mt][3] = f2tf(p[8 * LROW + 4]);
            }
#pragma unroll
            for (int nt = 0; nt < 4; nt++) {
                const float* p = Bsb + (wn * 32 + nt * 8 + gid) * LROW + kc + tig;
                bf[nt][0] = f2tf(p[0]);
                bf[nt][1] = f2tf(p[4]);
            }
#pragma unroll
            for (int mt = 0; mt < 4; mt++)
#pragma unroll
                for (int nt = 0; nt < 4; nt++)
                    mma8(acc[mt][nt], af[mt], bf[nt]);
        }
        __syncthreads();
    }

    // epilogue: scale by routing weight, atomically accumulate into out
#pragma unroll
    for (int mt = 0; mt < 4; mt++) {
        const int r0 = wm * 64 + mt * 16 + gid;
        const int gr0 = gbase + r0, gr1 = gr0 + 8;
        int tok0 = 0, tok1 = 0;
        float pw0 = 0.f, pw1 = 0.f;
        const bool ok0 = (gr0 < gend), ok1 = (gr1 < gend);
        if (ok0) { tok0 = g_perm[gr0]; pw0 = g_pw[gr0]; }
        if (ok1) { tok1 = g_perm[gr1]; pw1 = g_pw[gr1]; }
#pragma unroll
        for (int nt = 0; nt < 4; nt++) {
            const int col = nbase + wn * 32 + nt * 8 + tig * 2;
            const float b0v = s_bias[col - nbase], b1v = s_bias[col - nbase + 1];
            if (ok0) {
                atomicAdd(out + (size_t)tok0 * C + col,     pw0 * (acc[mt][nt][0] + b0v));
                atomicAdd(out + (size_t)tok0 * C + col + 1, pw0 * (acc[mt][nt][1] + b1v));
            }
            if (ok1) {
                atomicAdd(out + (size_t)tok1 * C + col,     pw1 * (acc[mt][nt][2] + b0v));
                atomicAdd(out + (size_t)tok1 * C + col + 1, pw1 * (acc[mt][nt][3] + b1v));
            }
        }
    }
}

// ---------------- launch ----------------
extern "C" void kernel_launch(void* const* d_in, const int* in_sizes, int n_in,
                              void* d_out, int out_size) {
    const float* x  = (const float*)d_in[0];
    const float* rw = (const float*)d_in[1];
    const float* w1 = (const float*)d_in[2];
    const float* b1 = (const float*)d_in[3];
    const float* w2 = (const float*)d_in[4];
    const float* b2 = (const float*)d_in[5];
    float* out = (float*)d_out;

    cudaFuncSetAttribute(gemm1_mma, cudaFuncAttributeMaxDynamicSharedMemorySize, GEMM_SMEM_BYTES);
    cudaFuncSetAttribute(gemm2_mma, cudaFuncAttributeMaxDynamicSharedMemorySize, GEMM_SMEM_BYTES);

    reset_kernel<<<1, 32>>>();
    router_kernel<<<T_TOK / 8, 256>>>(x, rw);
    scan_kernel<<<1, 32>>>();
    scatter_kernel<<<(TK + 255) / 256, 256>>>();
    zero_out_kernel<<<(T_TOK * (C / 4) + 255) / 256, 256>>>((float4*)out);
    gemm1_mma<<<dim3(FF / BN, TK / BM, E), 256, GEMM_SMEM_BYTES>>>(x, w1, b1);
    gemm2_mma<<<dim3(C / BN, TK / BM, E), 256, GEMM_SMEM_BYTES>>>(w2, b2, out);
}